// round 13
// baseline (speedup 1.0000x reference)
#include <cuda_runtime.h>
#include <cuda_fp16.h>
#include <cuda_bf16.h>
#include <cstdint>

#define N_NODES_MAX 50000
#define D 64

// Per-node record, 256 B:
//   halves [0..63]   = G = feat@W1 (fp16), natural column order
//   halves [64..127] = feat (fp16), PERMUTED: pos 64+8q+j holds
//                      feat[4q+j] for j<4, feat[32+4q+(j-4)] for j>=4
// Edge-lane l reads G cols [8l..8l+8) and its 8 feat cols each as ONE uint4.
__device__ __half g_rec[N_NODES_MAX * 128];
__device__ int g_idx_is64;

// gemm smem layout (dynamic):
//   sAf[2][128][SAF]  f32 feat tiles (double buffer)
//   Bf[4][8][32][2]   u32 B fragments
//   sG[128][SG]       fp16 G staging
#define SAF 68          // floats; 272B row = 17x16B (cp.async aligned), 4-bank shift
#define SG_STRIDE 72    // halves; 144B row, 16B-aligned flush
#define SAF_BYTES (128 * SAF * 4)          // 34816
#define BF_OFF    (2 * SAF_BYTES)          // 69632
#define SG_OFF    (BF_OFF + 8192)          // 77824
#define SMEM_BYTES (SG_OFF + 128 * SG_STRIDE * 2)   // 96256

__device__ __forceinline__ void cp_async16(void* smem_dst, const void* gsrc, bool pred) {
    uint32_t saddr = (uint32_t)__cvta_generic_to_shared(smem_dst);
    int p = pred ? 1 : 0;
    asm volatile(
        "{\n\t.reg .pred pp;\n\t"
        "setp.ne.b32 pp, %0, 0;\n\t"
        "@pp cp.async.cg.shared.global [%1], [%2], 16;\n\t}"
        :: "r"(p), "r"(saddr), "l"(gsrc));
}

// ---------------------------------------------------------------------------
// Node GEMM: cp.async double-buffered, 128-node tiles, 8-warp HMMA
// (fragment mapping validated in R8/R11). ~2 tiles per block.
// ---------------------------------------------------------------------------
__global__ void __launch_bounds__(256)
node_gemm_kernel(const float* __restrict__ feat,
                 const float* __restrict__ W1,
                 int n_nodes,
                 const long long* __restrict__ src_probe,
                 int n_edges) {
    extern __shared__ char dynsmem[];
    float* sAf[2] = { (float*)dynsmem, (float*)(dynsmem + SAF_BYTES) };
    uint32_t* BfP = (uint32_t*)(dynsmem + BF_OFF);
    __half* sG = (__half*)(dynsmem + SG_OFF);
#define BF(kt, nt, ln, j) BfP[((((kt) * 8 + (nt)) * 32 + (ln)) * 2) + (j)]

    const int tid = threadIdx.x;
    const int w = tid >> 5;          // warp 0..7
    const int lane = tid & 31;
    const int g = lane >> 2;
    const int tig = lane & 3;

    if (blockIdx.x == 0 && tid == 0) {
        int is64 = 1;
        int m = n_edges < 16 ? n_edges : 16;
        for (int i = 0; i < m; i++) {
            long long v = src_probe[i];
            if (v < 0 || v >= (long long)n_nodes) { is64 = 0; break; }
        }
        g_idx_is64 = is64;
    }

    // B fragments (warps 0-3 build k-tile = w): b0=(k=2tig,n) b1=(k+1) b2=(k+8) b3=(k+9)
    if (w < 4) {
        int k0 = w * 16 + 2 * tig;
#pragma unroll
        for (int nt = 0; nt < 8; nt++) {
            int n = nt * 8 + g;
            __half2 b01 = __floats2half2_rn(W1[k0 * 64 + n], W1[(k0 + 1) * 64 + n]);
            __half2 b23 = __floats2half2_rn(W1[(k0 + 8) * 64 + n], W1[(k0 + 9) * 64 + n]);
            BF(w, nt, lane, 0) = *(uint32_t*)&b01;
            BF(w, nt, lane, 1) = *(uint32_t*)&b23;
        }
    }

    const int n_tiles = (n_nodes + 127) >> 7;   // 391

    // prologue: prefetch first tile into buf 0
    {
        int t0 = blockIdx.x;
        if (t0 < n_tiles) {
            int base = t0 * 128;
            int rows = min(128, n_nodes - base);
#pragma unroll
            for (int p = 0; p < 8; p++) {
                int flat = p * 256 + tid;      // 128 rows x 16 float4
                int node = flat >> 4;
                int c = flat & 15;
                cp_async16(&sAf[0][node * SAF + c * 4],
                           &feat[(long long)(base + node) * 64 + c * 4],
                           node < rows);
            }
        }
        asm volatile("cp.async.commit_group;" ::: "memory");
    }

    int buf = 0;
    for (int t = blockIdx.x; t < n_tiles; t += gridDim.x) {
        const int base = t * 128;
        const int rows = min(128, n_nodes - base);

        // prefetch next tile into the other buffer
        {
            int tn = t + gridDim.x;
            if (tn < n_tiles) {
                int nbase = tn * 128;
                int nrows = min(128, n_nodes - nbase);
#pragma unroll
                for (int p = 0; p < 8; p++) {
                    int flat = p * 256 + tid;
                    int node = flat >> 4;
                    int c = flat & 15;
                    cp_async16(&sAf[buf ^ 1][node * SAF + c * 4],
                               &feat[(long long)(nbase + node) * 64 + c * 4],
                               node < nrows);
                }
            }
            asm volatile("cp.async.commit_group;" ::: "memory");
        }
        // wait until only the newest group (next tile) may be pending
        asm volatile("cp.async.wait_group 1;" ::: "memory");
        __syncthreads();   // current buf visible to all (also covers Bf on iter 0)

        const float* A = sAf[buf];

        // MMA: all 8 warps; warp w computes rows 16w .. 16w+15
        {
            int r0 = w * 16 + g;
            int r1 = r0 + 8;
            uint32_t a[4][4];
#pragma unroll
            for (int kt = 0; kt < 4; kt++) {
                int col = kt * 16 + 2 * tig;
                float2 f0 = *(const float2*)&A[r0 * SAF + col];
                float2 f1 = *(const float2*)&A[r1 * SAF + col];
                float2 f2 = *(const float2*)&A[r0 * SAF + col + 8];
                float2 f3 = *(const float2*)&A[r1 * SAF + col + 8];
                __half2 h0 = __floats2half2_rn(f0.x, f0.y);
                __half2 h1 = __floats2half2_rn(f1.x, f1.y);
                __half2 h2 = __floats2half2_rn(f2.x, f2.y);
                __half2 h3 = __floats2half2_rn(f3.x, f3.y);
                a[kt][0] = *(uint32_t*)&h0;
                a[kt][1] = *(uint32_t*)&h1;
                a[kt][2] = *(uint32_t*)&h2;
                a[kt][3] = *(uint32_t*)&h3;
            }
#pragma unroll
            for (int nt = 0; nt < 8; nt++) {
                float d0 = 0.f, d1 = 0.f, d2 = 0.f, d3 = 0.f;
#pragma unroll
                for (int kt = 0; kt < 4; kt++) {
                    asm volatile(
                        "mma.sync.aligned.m16n8k16.row.col.f32.f16.f16.f32 "
                        "{%0,%1,%2,%3}, {%4,%5,%6,%7}, {%8,%9}, {%0,%1,%2,%3};"
                        : "+f"(d0), "+f"(d1), "+f"(d2), "+f"(d3)
                        : "r"(a[kt][0]), "r"(a[kt][1]), "r"(a[kt][2]), "r"(a[kt][3]),
                          "r"(BF(kt, nt, lane, 0)), "r"(BF(kt, nt, lane, 1)));
                }
                int cc = nt * 8 + 2 * tig;
                *(__half2*)&sG[r0 * SG_STRIDE + cc] = __floats2half2_rn(d0, d1);
                *(__half2*)&sG[r1 * SG_STRIDE + cc] = __floats2half2_rn(d2, d3);
            }
        }

        // permuted F half: f32 smem -> fp16 gmem (node = tid/2, hf = tid&1)
        {
            int node = tid >> 1;
            int hf = tid & 1;
            if (node < rows) {
                const float* srow = &A[node * SAF + (hf ? 32 : 0)];
                __half* drow = &g_rec[(long long)(base + node) * 128 + 64 + (hf ? 4 : 0)];
#pragma unroll
                for (int q = 0; q < 8; q++) {
                    float4 fv = *(const float4*)&srow[4 * q];
                    __half2 v0 = __floats2half2_rn(fv.x, fv.y);
                    __half2 v1 = __floats2half2_rn(fv.z, fv.w);
                    uint2 u;
                    u.x = *(uint32_t*)&v0;
                    u.y = *(uint32_t*)&v1;
                    *(uint2*)&drow[8 * q] = u;
                }
            }
        }
        __syncthreads();   // sG complete before flush; sAf[buf] fully consumed

        // flush G region -> g_rec, coalesced uint4
#pragma unroll
        for (int p = 0; p < 4; p++) {
            int flat = p * 256 + tid;          // 128 nodes x 8 uint4
            int node = flat >> 3;
            int c = flat & 7;
            if (node < rows) {
                uint4 v = *(const uint4*)&sG[node * SG_STRIDE + c * 8];
                ((uint4*)g_rec)[(long long)(base + node) * 16 + c] = v;
            }
        }
        __syncthreads();   // sG reusable next iteration
        buf ^= 1;
    }

    cudaTriggerProgrammaticLaunchCompletion();
}

// ---------------------------------------------------------------------------
// Edge kernel (unchanged — at the LTS roofline), PDL-launched.
// ---------------------------------------------------------------------------
__global__ void __launch_bounds__(256, 4)
edge_kernel(const void* __restrict__ src_idx,
            const void* __restrict__ dst_idx,
            const float* __restrict__ b1,
            const float* __restrict__ W2,
            const float* __restrict__ b2,
            float* __restrict__ out,
            int n_edges) {
    const int l = threadIdx.x & 7;
    const int groupInBlock = threadIdx.x >> 3;
    const int gid = (int)blockIdx.x * 32 + groupInBlock;
    const int totalGroups = (int)gridDim.x * 32;

    const float4* B14 = (const float4*)b1;
    const float4* W24 = (const float4*)W2;
    float4 b1a = __ldg(&B14[2 * l]);
    float4 b1b = __ldg(&B14[2 * l + 1]);
    float4 w2a = __ldg(&W24[2 * l]);
    float4 w2b = __ldg(&W24[2 * l + 1]);
    float b2v = __ldg(&b2[0]);

    cudaGridDependencySynchronize();

    const int is64 = g_idx_is64;
    const uint4* R16 = (const uint4*)g_rec;
    float4* O4 = (float4*)out;

    for (int e0 = 2 * gid; e0 < n_edges; e0 += 2 * totalGroups) {
        int e1 = e0 + 1;
        bool hasB = (e1 < n_edges);

        long long sA, dA, sB = 0, dB = 0;
        if (is64) {
            longlong2 sp = __ldg(&((const longlong2*)src_idx)[e0 >> 1]);
            longlong2 dp = __ldg(&((const longlong2*)dst_idx)[e0 >> 1]);
            sA = sp.x; dA = dp.x; sB = sp.y; dB = dp.y;
        } else {
            int2 sp = __ldg(&((const int2*)src_idx)[e0 >> 1]);
            int2 dp = __ldg(&((const int2*)dst_idx)[e0 >> 1]);
            sA = sp.x; dA = dp.x; sB = sp.y; dB = dp.y;
        }

        uint4 gsA = __ldg(&R16[sA * 16 + l]);
        uint4 gdA = __ldg(&R16[dA * 16 + l]);
        uint4 fdA = __ldg(&R16[dA * 16 + 8 + l]);
        uint4 gsB, gdB, fdB;
        if (hasB) {
            gsB = __ldg(&R16[sB * 16 + l]);
            gdB = __ldg(&R16[dB * 16 + l]);
            fdB = __ldg(&R16[dB * 16 + 8 + l]);
        }

#define EDGE_BODY(GS, GD, FD, EIDX)                                            \
        {                                                                      \
            float2 s0 = __half22float2(*(const __half2*)&GS.x);                \
            float2 s1 = __half22float2(*(const __half2*)&GS.y);                \
            float2 s2 = __half22float2(*(const __half2*)&GS.z);                \
            float2 s3 = __half22float2(*(const __half2*)&GS.w);                \
            float2 dd0 = __half22float2(*(const __half2*)&GD.x);               \
            float2 dd1 = __half22float2(*(const __half2*)&GD.y);               \
            float2 dd2 = __half22float2(*(const __half2*)&GD.z);               \
            float2 dd3 = __half22float2(*(const __half2*)&GD.w);               \
            float h0 = fmaxf(s0.x - dd0.x + b1a.x, 0.f);                       \
            float h1 = fmaxf(s0.y - dd0.y + b1a.y, 0.f);                       \
            float h2 = fmaxf(s1.x - dd1.x + b1a.z, 0.f);                       \
            float h3 = fmaxf(s1.y - dd1.y + b1a.w, 0.f);                       \
            float h4 = fmaxf(s2.x - dd2.x + b1b.x, 0.f);                       \
            float h5 = fmaxf(s2.y - dd2.y + b1b.y, 0.f);                       \
            float h6 = fmaxf(s3.x - dd3.x + b1b.z, 0.f);                       \
            float h7 = fmaxf(s3.y - dd3.y + b1b.w, 0.f);                       \
            float p = h0 * w2a.x;                                              \
            p = fmaf(h1, w2a.y, p); p = fmaf(h2, w2a.z, p);                    \
            p = fmaf(h3, w2a.w, p); p = fmaf(h4, w2b.x, p);                    \
            p = fmaf(h5, w2b.y, p); p = fmaf(h6, w2b.z, p);                    \
            p = fmaf(h7, w2b.w, p);                                            \
            p += __shfl_xor_sync(0xffffffffu, p, 1, 8);                        \
            p += __shfl_xor_sync(0xffffffffu, p, 2, 8);                        \
            p += __shfl_xor_sync(0xffffffffu, p, 4, 8);                        \
            float aa = __expf(-fmaxf(p + b2v, 0.f));                           \
            float2 f0 = __half22float2(*(const __half2*)&FD.x);                \
            float2 f1 = __half22float2(*(const __half2*)&FD.y);                \
            float2 f2 = __half22float2(*(const __half2*)&FD.z);                \
            float2 f3 = __half22float2(*(const __half2*)&FD.w);                \
            float4 oA = make_float4(aa * f0.x, aa * f0.y, aa * f1.x, aa * f1.y); \
            float4 oB = make_float4(aa * f2.x, aa * f2.y, aa * f3.x, aa * f3.y); \
            long long ob = (long long)(EIDX) * 16;                             \
            O4[ob + l] = oA;                                                   \
            O4[ob + l + 8] = oB;                                               \
        }

        EDGE_BODY(gsA, gdA, fdA, e0)
        if (hasB) EDGE_BODY(gsB, gdB, fdB, e1)
#undef EDGE_BODY
    }
}

// ---------------------------------------------------------------------------
// kernel_launch — inputs (metadata order):
//   0 features [50000,64] f32
//   1 src_idx  [800000]   int64 (or int32, detected)
//   2 dst_idx  [800000]   int64/int32
//   3 W1 [64,64] f32   4 b1 [64] f32   5 W2 [64,1] f32   6 b2 [1] f32
// output: [800000, 64] f32
// ---------------------------------------------------------------------------
extern "C" void kernel_launch(void* const* d_in, const int* in_sizes, int n_in,
                              void* d_out, int out_size) {
    const float* feat = (const float*)d_in[0];
    const void*  src  = d_in[1];
    const void*  dst  = d_in[2];
    const float* W1   = (const float*)d_in[3];
    const float* b1   = (const float*)d_in[4];
    const float* W2   = (const float*)d_in[5];
    const float* b2   = (const float*)d_in[6];
    float* out = (float*)d_out;

    int n_nodes = in_sizes[0] / D;
    int n_edges = in_sizes[1];

    int n_tiles = (n_nodes + 127) / 128;         // 391
    int gemm_grid = (n_tiles + 1) / 2;           // 196 (~2 tiles/block, pipelined)

    static int smem_set = 0;
    if (!smem_set) {
        cudaFuncSetAttribute(node_gemm_kernel,
                             cudaFuncAttributeMaxDynamicSharedMemorySize,
                             SMEM_BYTES);
        smem_set = 1;
    }
    node_gemm_kernel<<<gemm_grid, 256, SMEM_BYTES>>>(feat, W1, n_nodes,
                                                     (const long long*)src,
                                                     n_edges);

    cudaLaunchConfig_t cfg = {};
    cfg.gridDim = dim3(1184, 1, 1);
    cfg.blockDim = dim3(256, 1, 1);
    cfg.dynamicSmemBytes = 0;
    cfg.stream = 0;
    cudaLaunchAttribute attrs[1];
    attrs[0].id = cudaLaunchAttributeProgrammaticStreamSerialization;
    attrs[0].val.programmaticStreamSerializationAllowed = 1;
    cfg.attrs = attrs;
    cfg.numAttrs = 1;
    cudaLaunchKernelEx(&cfg, edge_kernel, src, dst, b1, W2, b2, out, n_edges);
}